// round 14
// baseline (speedup 1.0000x reference)
#include <cuda_runtime.h>
#include <cstdint>
#include <stdint.h>
#include <math.h>

#define HDIM   64
#define CNEI   32
#define NBLK   8
#define NTHR   1024
#define TROWS  32
#define NROWS  48
#define WPACK  1128

struct __align__(16) PushBlk { float vec[HDIM]; float en[8]; };  // 288 B
#define PUSH_BYTES 288
#define EXPECT_TX ((NBLK - 1) * PUSH_BYTES)

struct __align__(16) Smem {
    PushBlk rx[2][NBLK];              // 4608 B
    float pe[TROWS][HDIM];            // 8 KB
    float cache[NROWS][HDIM];         // 12 KB
    float wts[WPACK];                 // 4.5 KB
    float red_s[8][HDIM];             // 2 KB
    float red_f[4][8][HDIM];          // 8 KB
    float bias_s[2][HDIM];
    float pos[64];
    float dt[32];
    int   tok[TROWS];
    int   ne_br[CNEI][4];
    int   edge0[4];
    int   x0;
    unsigned long long mbar[2];
};

__device__ __forceinline__ float gelu_exact(float v) {
    return 0.5f * v * (1.0f + erff(v * 0.70710678118654752440f));
}
__device__ __forceinline__ uint32_t mapa_u32(uint32_t addr, uint32_t rank) {
    uint32_t d;
    asm("mapa.shared::cluster.u32 %0, %1, %2;" : "=r"(d) : "r"(addr), "r"(rank));
    return d;
}
__device__ __forceinline__ void cluster_sync_all() {
    asm volatile("barrier.cluster.arrive.aligned;" ::: "memory");
    asm volatile("barrier.cluster.wait.aligned;"   ::: "memory");
}
__device__ __forceinline__ void mbar_init(uint32_t a, uint32_t cnt) {
    asm volatile("mbarrier.init.shared.b64 [%0], %1;" :: "r"(a), "r"(cnt) : "memory");
}
__device__ __forceinline__ void mbar_arrive_expect(uint32_t a, uint32_t tx) {
    asm volatile("mbarrier.arrive.expect_tx.shared.b64 _, [%0], %1;" :: "r"(a), "r"(tx) : "memory");
}
__device__ __forceinline__ void mbar_wait(uint32_t a, uint32_t parity) {
    uint32_t done;
    asm volatile(
        "{\n\t.reg .pred p;\n\t"
        "mbarrier.try_wait.parity.acquire.cta.shared::cta.b64 p, [%1], %2;\n\t"
        "selp.b32 %0, 1, 0, p;\n\t}"
        : "=r"(done) : "r"(a), "r"(parity) : "memory");
    if (!done) {
        asm volatile(
            "{\n\t.reg .pred P1;\n\t"
            "WAIT_LOOP_%=:\n\t"
            "mbarrier.try_wait.parity.acquire.cta.shared::cta.b64 P1, [%0], %1, 0x989680;\n\t"
            "@P1 bra.uni WAIT_DONE_%=;\n\t"
            "bra.uni WAIT_LOOP_%=;\n\t"
            "WAIT_DONE_%=:\n\t}"
            :: "r"(a), "r"(parity) : "memory");
    }
}
__device__ __forceinline__ void bulk_s2s(uint32_t dst, uint32_t src, uint32_t bytes, uint32_t rmbar) {
    asm volatile(
        "cp.async.bulk.shared::cluster.shared::cta.mbarrier::complete_tx::bytes [%0], [%1], %2, [%3];"
        :: "r"(dst), "r"(src), "r"(bytes), "r"(rmbar) : "memory");
}

__global__ __launch_bounds__(NTHR, 1) __cluster_dims__(NBLK, 1, 1)
void bralm_kernel(const float* __restrict__ W,
                  const float* __restrict__ Bb,
                  const float* __restrict__ POS,
                  const int*   __restrict__ SE,
                  const int*   __restrict__ NE,
                  const int*   __restrict__ NN,
                  const int*   __restrict__ X0P,
                  const int*   __restrict__ MNTP,
                  float* __restrict__ out,
                  int out_size, int L)
{
    extern __shared__ __align__(16) char smem_raw[];
    Smem* S = (Smem*)smem_raw;
    __shared__ float e_vec[HDIM];

    const int tid  = threadIdx.x;
    const int lane = tid & 31;
    uint32_t myrank;
    asm("mov.u32 %0, %%cluster_ctarank;" : "=r"(myrank));

    const uint32_t mbar_a0 = (uint32_t)__cvta_generic_to_shared(&S->mbar[0]);
    const uint32_t mbar_a1 = (uint32_t)__cvta_generic_to_shared(&S->mbar[1]);

    int T = (MNTP != nullptr) ? MNTP[0] : 32;
    if (T < 0) T = 0;
    if (L + T > NROWS) T = NROWS - L;
    if (T > TROWS)     T = TROWS;

    // ---------------- init ----------------
    if (tid == 0) { mbar_init(mbar_a0, 1); mbar_init(mbar_a1, 1); }
    if (tid < HDIM / 2)
        S->dt[tid] = (float)pow(10000.0, (double)(2 * tid) / 64.0);
    for (int i = tid; i < NROWS * HDIM; i += NTHR)
        S->cache[i >> 6][i & 63] = 0.0f;
    if (tid < 64) S->pos[tid] = POS[tid];
    __syncthreads();

    for (int idx = tid; idx < TROWS * HDIM; idx += NTHR) {
        int i = idx >> 6, h = idx & 63;
        float argf = (float)i * S->dt[h >> 1];
        double ad = (double)argf;
        double kq2 = rint(ad * 0.15915494309189535);
        double r   = fma(-kq2, 6.283185307179586, ad);
        S->pe[i][h] = (h & 1) ? cosf((float)r) : sinf((float)r);
    }
    {   // packed triangular softmax table, rows c = 1..47
        int w = tid >> 5;
        for (int c = w + 1; c < NROWS; c += 32) {
            float v0 = (lane      < c) ? S->pos[lane]      : -INFINITY;
            float v1 = (lane + 32 < c) ? S->pos[lane + 32] : -INFINITY;
            float m = fmaxf(v0, v1);
            #pragma unroll
            for (int off = 16; off > 0; off >>= 1)
                m = fmaxf(m, __shfl_xor_sync(0xffffffffu, m, off));
            float u0 = (lane      < c) ? expf(v0 - m) : 0.0f;
            float u1 = (lane + 32 < c) ? expf(v1 - m) : 0.0f;
            float s = u0 + u1;
            #pragma unroll
            for (int off = 16; off > 0; off >>= 1)
                s += __shfl_xor_sync(0xffffffffu, s, off);
            int base = c * (c - 1) / 2;
            if (lane      < c) S->wts[base + lane]      = u0 / s;
            if (lane + 32 < c) S->wts[base + lane + 32] = u1 / s;
        }
    }
    __syncthreads();

    const int g   = tid >> 8;
    const int tc  = tid & 255;
    const int hp  = tc >> 4;
    const int kq  = tc & 15;
    const int w2  = tc >> 5;

    // ---------------- prompt: 2 barriers/step, role-split (R13 champion) ----------------
    if (tid < HDIM) e_vec[tid] = 1.0f / 64.0f;

    float4 wvp[4];
    if (tid >= 256 && tid < 512 && L > 0) {
        const float4* Wb = (const float4*)(W + (size_t)SE[0] * (HDIM * HDIM));
        #pragma unroll
        for (int r = 0; r < 4; ++r) wvp[r] = Wb[(hp * 4 + r) * 16 + kq];
    }
    if (tid >= 64 && tid < 128 && L > 0)
        S->bias_s[0][tid - 64] = Bb[(size_t)SE[0] * HDIM + (tid - 64)];
    __syncthreads();

    for (int i = 0; i < L; ++i) {
        if (tid >= 256 && tid < 512) {
            float4 a4 = make_float4(0.f, 0.f, 0.f, 0.f);
            #pragma unroll
            for (int r = 0; r < 4; ++r) {
                float ev = e_vec[hp * 4 + r];
                a4.x = fmaf(ev, wvp[r].x, a4.x); a4.y = fmaf(ev, wvp[r].y, a4.y);
                a4.z = fmaf(ev, wvp[r].z, a4.z); a4.w = fmaf(ev, wvp[r].w, a4.w);
            }
            a4.x += __shfl_xor_sync(0xffffffffu, a4.x, 16);
            a4.y += __shfl_xor_sync(0xffffffffu, a4.y, 16);
            a4.z += __shfl_xor_sync(0xffffffffu, a4.z, 16);
            a4.w += __shfl_xor_sync(0xffffffffu, a4.w, 16);
            if ((tc & 16) == 0)
                *(float4*)&S->red_f[0][w2][kq * 4] = a4;
        }
        __syncthreads();

        if (tid >= 256 && tid < 512 && i + 1 < L) {
            const float4* Wb = (const float4*)(W + (size_t)SE[i + 1] * (HDIM * HDIM));
            #pragma unroll
            for (int r = 0; r < 4; ++r) wvp[r] = Wb[(hp * 4 + r) * 16 + kq];
        }
        if (tid >= 64 && tid < 128 && i + 1 < L)
            S->bias_s[(i + 1) & 1][tid - 64] = Bb[(size_t)SE[i + 1] * HDIM + (tid - 64)];
        if (tid < 64) {
            float v = 0.0f;
            #pragma unroll
            for (int q = 0; q < 8; ++q) v += S->red_f[0][q][tid];
            v += S->bias_s[i & 1][tid] + S->pe[i][tid];
            float gev = gelu_exact(v);
            S->cache[i][tid] = gev;
            int base = (i + 1) * i / 2;
            float acc = 0.0f;
            for (int j = 0; j < i; ++j)
                acc = fmaf(S->wts[base + j], S->cache[j][tid], acc);
            e_vec[tid] = fmaf(S->wts[base + i], gev, acc);
        }
        __syncthreads();
    }

    // ---------------- generation priming (e_vec holds e for curr=L) ----------------
    if (tid == 0) S->x0 = (X0P != nullptr) ? X0P[0] : 7;
    __syncthreads();
    const int x0v = S->x0;

    int nn_reg = 0, nn_next = 0;
    if (tid < 32) {
        nn_reg = NN[(size_t)x0v * CNEI + tid];
        #pragma unroll
        for (int c = 0; c < 4; ++c)
            S->ne_br[tid][c] = NE[(size_t)nn_reg * CNEI + myrank * 4 + c];
    }
    if (tid < 4) S->edge0[tid] = NE[(size_t)x0v * CNEI + myrank * 4 + tid];
    __syncthreads();

    float4 wv[4];
    {
        const float4* Wb = (const float4*)(W + (size_t)S->edge0[g] * (HDIM * HDIM));
        #pragma unroll
        for (int r = 0; r < 4; ++r) wv[r] = Wb[(hp * 4 + r) * 16 + kq];
    }
    float bias_r = 0.0f;
    if (tid < 256) bias_r = Bb[(size_t)S->edge0[tid >> 6] * HDIM + (tid & 63)];

    cluster_sync_all();
    __syncthreads();

    // ---------------- generation loop ----------------
    for (int t = 0; t < T; ++t) {
        const int curr = L + t;
        const int cb   = t & 1;
        const uint32_t mb = cb ? mbar_a1 : mbar_a0;

        if (tid == 0) mbar_arrive_expect(mb, EXPECT_TX);

        // 1) matvec partials
        {
            float4 a4 = make_float4(0.f, 0.f, 0.f, 0.f);
            #pragma unroll
            for (int r = 0; r < 4; ++r) {
                float ev = e_vec[hp * 4 + r];
                a4.x = fmaf(ev, wv[r].x, a4.x); a4.y = fmaf(ev, wv[r].y, a4.y);
                a4.z = fmaf(ev, wv[r].z, a4.z); a4.w = fmaf(ev, wv[r].w, a4.w);
            }
            a4.x += __shfl_xor_sync(0xffffffffu, a4.x, 16);
            a4.y += __shfl_xor_sync(0xffffffffu, a4.y, 16);
            a4.z += __shfl_xor_sync(0xffffffffu, a4.z, 16);
            a4.w += __shfl_xor_sync(0xffffffffu, a4.w, 16);
            if ((tc & 16) == 0)
                *(float4*)&S->red_f[g][w2][kq * 4] = a4;
        }
        __syncthreads();   // bar1

        // 2) combine+gelu (ge kept in register) + energies into push block
        //    | NE gathers (warp0) | pooled partials (tid>=512)
        float ge = 0.0f;
        if (tid < 256) {
            if (tid < 32 && t > 0) {
                nn_reg = nn_next;
                int e0 = NE[(size_t)nn_reg * CNEI + myrank * 4 + 0];
                int e1 = NE[(size_t)nn_reg * CNEI + myrank * 4 + 1];
                int e2 = NE[(size_t)nn_reg * CNEI + myrank * 4 + 2];
                int e3 = NE[(size_t)nn_reg * CNEI + myrank * 4 + 3];
                S->ne_br[lane][0] = e0; S->ne_br[lane][1] = e1;
                S->ne_br[lane][2] = e2; S->ne_br[lane][3] = e3;
            }
            int cand = tid >> 6, kk = tid & 63;
            float v = 0.0f;
            #pragma unroll
            for (int q = 0; q < 8; ++q) v += S->red_f[cand][q][kk];
            v += bias_r + S->pe[t][kk];
            ge = gelu_exact(v);
            float sq = ge * ge;
            #pragma unroll
            for (int off = 16; off > 0; off >>= 1)
                sq += __shfl_xor_sync(0xffffffffu, sq, off);
            if (lane == 0) S->rx[cb][myrank].en[tid >> 5] = sq;   // cand*2+half
        } else if (tid >= 512 && t + 1 < T) {
            int p = (tid >> 6) - 8, k = tid & 63;
            int base1 = (curr + 1) * curr / 2;
            float acc = 0.0f;
            for (int j = p; j < curr; j += 8)
                acc = fmaf(S->wts[base1 + j], S->cache[j][k], acc);
            S->red_s[p][k] = acc;
        }
        __syncthreads();   // bar2 (full): energies + red_s visible CTA-wide

        // 2b) local-best select: only the winning candidate's 64 threads store vec
        if (tid < 256) {
            float4 e01 = *(const float4*)&S->rx[cb][myrank].en[0];
            float4 e23 = *(const float4*)&S->rx[cb][myrank].en[4];
            float s0 = e01.x + e01.y, s1 = e01.z + e01.w;
            float s2 = e23.x + e23.y, s3 = e23.z + e23.w;
            int lb = 0; float bb = s0;
            if (s1 > bb) { bb = s1; lb = 1; }
            if (s2 > bb) { bb = s2; lb = 2; }
            if (s3 > bb) { bb = s3; lb = 3; }
            if ((tid >> 6) == lb)
                S->rx[cb][myrank].vec[tid & 63] = ge;
            asm volatile("bar.sync 1, 256;" ::: "memory");   // warps 0-7 only
        }

        // 3) distributed push: lanes 0-6 each one 288 B bulk copy
        if (tid < NBLK - 1) {
            asm volatile("fence.proxy.async.shared::cta;" ::: "memory");
            uint32_t r = (myrank + 1 + (uint32_t)tid) & (NBLK - 1);
            uint32_t src = (uint32_t)__cvta_generic_to_shared(&S->rx[cb][myrank]);
            bulk_s2s(mapa_u32(src, r), src, PUSH_BYTES, mapa_u32(mb, r));
        }

        // 4) wait for all 7 peer blocks
        mbar_wait(mb, (uint32_t)((t >> 1) & 1));

        // 5) redundant per-warp argmax (uint order == float order, sumsq >= 0)
        int bi;
        {
            int rr = lane >> 2, cl = lane & 3;
            float2 eh = *(const float2*)&S->rx[cb][rr].en[cl * 2];
            float en = eh.x + eh.y;
            unsigned mx = __reduce_max_sync(0xffffffffu, __float_as_uint(en));
            unsigned msk = __ballot_sync(0xffffffffu, __float_as_uint(en) == mx);
            bi = __ffs(msk) - 1;      // first occurrence == jnp.argmax
        }
        if (tid < 32) {
            int y = __shfl_sync(0xffffffffu, nn_reg, bi);
            if (lane == 0) S->tok[t] = y;
            nn_next = NN[(size_t)y * CNEI + lane];
        }

        // 6) next-step weight/bias loads + winner (pushed local-best) read
        {
            int edge_g = S->ne_br[bi][g];
            const float4* Wb = (const float4*)(W + (size_t)edge_g * (HDIM * HDIM));
            #pragma unroll
            for (int r = 0; r < 4; ++r) wv[r] = Wb[(hp * 4 + r) * 16 + kq];
        }
        if (tid < 256)
            bias_r = Bb[(size_t)S->ne_br[bi][tid >> 6] * HDIM + (tid & 63)];

        if (tid < HDIM) {
            float win = S->rx[cb][bi >> 2].vec[tid];
            S->cache[curr][tid] = win;
            if (t + 1 < T) {
                int base1 = (curr + 1) * curr / 2;
                float ee = 0.0f;
                #pragma unroll
                for (int q = 0; q < 8; ++q) ee += S->red_s[q][tid];
                e_vec[tid] = fmaf(S->wts[base1 + curr], win, ee);
            }
        }
        __syncthreads();   // bar4
    }

    // drain outgoing bulk reads before exit
    cluster_sync_all();
    __syncthreads();

    // ---------------- output (CTA 0) ----------------
    if (blockIdx.x == 0) {
        int ncache = (L + T) * HDIM;
        for (int i = tid; i < out_size; i += NTHR) {
            float v;
            if (i < ncache) v = S->cache[i >> 6][i & 63];
            else {
                int tt = i - ncache;
                v = (tt < T) ? (float)S->tok[tt] : 0.0f;
            }
            out[i] = v;
        }
    }
}

extern "C" void kernel_launch(void* const* d_in, const int* in_sizes, int n_in,
                              void* d_out, int out_size) {
    const float* W   = (const float*)d_in[0];
    const float* B   = (const float*)d_in[1];
    const float* POS = (const float*)d_in[2];
    const int*   SE  = (const int*)d_in[3];
    const int*   NE  = (const int*)d_in[4];
    const int*   NN  = (const int*)d_in[5];
    const int*   X0  = (n_in > 6) ? (const int*)d_in[6] : nullptr;
    const int*   MNT = (n_in > 7) ? (const int*)d_in[7] : nullptr;
    int L = in_sizes[3];

    cudaFuncSetAttribute(bralm_kernel,
                         cudaFuncAttributeMaxDynamicSharedMemorySize,
                         (int)sizeof(Smem));
    bralm_kernel<<<NBLK, NTHR, sizeof(Smem)>>>(W, B, POS, SE, NE, NN, X0, MNT,
                                               (float*)d_out, out_size, L);
}

// round 15
// speedup vs baseline: 1.0345x; 1.0345x over previous
#include <cuda_runtime.h>
#include <cstdint>
#include <stdint.h>
#include <math.h>

#define HDIM   64
#define CNEI   32
#define NBLK   8
#define NTHR   1024
#define TROWS  32
#define NROWS  48
#define WPACK  1128

struct __align__(16) PushBlk { float vec[4][HDIM]; float en[8]; };  // 1056 B
#define PUSH_BYTES 1056
#define EXPECT_TX ((NBLK - 1) * PUSH_BYTES)

struct __align__(16) Smem {
    PushBlk rx[2][NBLK];              // 16896 B
    float pe[TROWS][HDIM];            // 8 KB
    float cache[NROWS][HDIM];         // 12 KB
    float wts[WPACK];                 // 4.5 KB
    float red_s[8][HDIM];             // 2 KB
    float red_f[4][8][HDIM];          // 8 KB
    float bias_s[2][HDIM];
    float pos[64];
    float dt[32];
    int   tok[TROWS];
    int   ne_br[CNEI][4];
    int   edge0[4];
    int   x0;
    unsigned long long mbar[2];
};

__device__ __forceinline__ float gelu_exact(float v) {
    return 0.5f * v * (1.0f + erff(v * 0.70710678118654752440f));
}
__device__ __forceinline__ uint32_t mapa_u32(uint32_t addr, uint32_t rank) {
    uint32_t d;
    asm("mapa.shared::cluster.u32 %0, %1, %2;" : "=r"(d) : "r"(addr), "r"(rank));
    return d;
}
__device__ __forceinline__ void cluster_sync_all() {
    asm volatile("barrier.cluster.arrive.aligned;" ::: "memory");
    asm volatile("barrier.cluster.wait.aligned;"   ::: "memory");
}
__device__ __forceinline__ void mbar_init(uint32_t a, uint32_t cnt) {
    asm volatile("mbarrier.init.shared.b64 [%0], %1;" :: "r"(a), "r"(cnt) : "memory");
}
__device__ __forceinline__ void mbar_arrive_expect(uint32_t a, uint32_t tx) {
    asm volatile("mbarrier.arrive.expect_tx.shared.b64 _, [%0], %1;" :: "r"(a), "r"(tx) : "memory");
}
__device__ __forceinline__ void mbar_wait(uint32_t a, uint32_t parity) {
    uint32_t done;
    asm volatile(
        "{\n\t.reg .pred p;\n\t"
        "mbarrier.try_wait.parity.acquire.cta.shared::cta.b64 p, [%1], %2;\n\t"
        "selp.b32 %0, 1, 0, p;\n\t}"
        : "=r"(done) : "r"(a), "r"(parity) : "memory");
    if (!done) {
        asm volatile(
            "{\n\t.reg .pred P1;\n\t"
            "WAIT_LOOP_%=:\n\t"
            "mbarrier.try_wait.parity.acquire.cta.shared::cta.b64 P1, [%0], %1, 0x989680;\n\t"
            "@P1 bra.uni WAIT_DONE_%=;\n\t"
            "bra.uni WAIT_LOOP_%=;\n\t"
            "WAIT_DONE_%=:\n\t}"
            :: "r"(a), "r"(parity) : "memory");
    }
}
__device__ __forceinline__ void bulk_s2s(uint32_t dst, uint32_t src, uint32_t bytes, uint32_t rmbar) {
    asm volatile(
        "cp.async.bulk.shared::cluster.shared::cta.mbarrier::complete_tx::bytes [%0], [%1], %2, [%3];"
        :: "r"(dst), "r"(src), "r"(bytes), "r"(rmbar) : "memory");
}

__global__ __launch_bounds__(NTHR, 1) __cluster_dims__(NBLK, 1, 1)
void bralm_kernel(const float* __restrict__ W,
                  const float* __restrict__ Bb,
                  const float* __restrict__ POS,
                  const int*   __restrict__ SE,
                  const int*   __restrict__ NE,
                  const int*   __restrict__ NN,
                  const int*   __restrict__ X0P,
                  const int*   __restrict__ MNTP,
                  float* __restrict__ out,
                  int out_size, int L)
{
    extern __shared__ __align__(16) char smem_raw[];
    Smem* S = (Smem*)smem_raw;
    __shared__ float e_vec[HDIM];

    const int tid  = threadIdx.x;
    const int lane = tid & 31;
    uint32_t myrank;
    asm("mov.u32 %0, %%cluster_ctarank;" : "=r"(myrank));

    const uint32_t mbar_a0 = (uint32_t)__cvta_generic_to_shared(&S->mbar[0]);
    const uint32_t mbar_a1 = (uint32_t)__cvta_generic_to_shared(&S->mbar[1]);

    int T = (MNTP != nullptr) ? MNTP[0] : 32;
    if (T < 0) T = 0;
    if (L + T > NROWS) T = NROWS - L;
    if (T > TROWS)     T = TROWS;

    // ---------------- init ----------------
    if (tid == 0) { mbar_init(mbar_a0, 1); mbar_init(mbar_a1, 1); }
    if (tid < HDIM / 2)
        S->dt[tid] = (float)pow(10000.0, (double)(2 * tid) / 64.0);
    for (int i = tid; i < NROWS * HDIM; i += NTHR)
        S->cache[i >> 6][i & 63] = 0.0f;
    if (tid < 64) S->pos[tid] = POS[tid];
    __syncthreads();

    for (int idx = tid; idx < TROWS * HDIM; idx += NTHR) {
        int i = idx >> 6, h = idx & 63;
        float argf = (float)i * S->dt[h >> 1];
        double ad = (double)argf;
        double kq2 = rint(ad * 0.15915494309189535);
        double r   = fma(-kq2, 6.283185307179586, ad);
        S->pe[i][h] = (h & 1) ? cosf((float)r) : sinf((float)r);
    }
    {   // packed triangular softmax table, rows c = 1..47
        int w = tid >> 5;
        for (int c = w + 1; c < NROWS; c += 32) {
            float v0 = (lane      < c) ? S->pos[lane]      : -INFINITY;
            float v1 = (lane + 32 < c) ? S->pos[lane + 32] : -INFINITY;
            float m = fmaxf(v0, v1);
            #pragma unroll
            for (int off = 16; off > 0; off >>= 1)
                m = fmaxf(m, __shfl_xor_sync(0xffffffffu, m, off));
            float u0 = (lane      < c) ? expf(v0 - m) : 0.0f;
            float u1 = (lane + 32 < c) ? expf(v1 - m) : 0.0f;
            float s = u0 + u1;
            #pragma unroll
            for (int off = 16; off > 0; off >>= 1)
                s += __shfl_xor_sync(0xffffffffu, s, off);
            int base = c * (c - 1) / 2;
            if (lane      < c) S->wts[base + lane]      = u0 / s;
            if (lane + 32 < c) S->wts[base + lane + 32] = u1 / s;
        }
    }
    __syncthreads();

    const int g   = tid >> 8;
    const int tc  = tid & 255;
    const int hp  = tc >> 4;
    const int kq  = tc & 15;
    const int w2  = tc >> 5;

    // ---------------- prompt: 2 barriers/step, role-split (R13 champion) ----------------
    if (tid < HDIM) e_vec[tid] = 1.0f / 64.0f;

    float4 wvp[4];
    if (tid >= 256 && tid < 512 && L > 0) {
        const float4* Wb = (const float4*)(W + (size_t)SE[0] * (HDIM * HDIM));
        #pragma unroll
        for (int r = 0; r < 4; ++r) wvp[r] = Wb[(hp * 4 + r) * 16 + kq];
    }
    if (tid >= 64 && tid < 128 && L > 0)
        S->bias_s[0][tid - 64] = Bb[(size_t)SE[0] * HDIM + (tid - 64)];
    __syncthreads();

    for (int i = 0; i < L; ++i) {
        if (tid >= 256 && tid < 512) {
            float4 a4 = make_float4(0.f, 0.f, 0.f, 0.f);
            #pragma unroll
            for (int r = 0; r < 4; ++r) {
                float ev = e_vec[hp * 4 + r];
                a4.x = fmaf(ev, wvp[r].x, a4.x); a4.y = fmaf(ev, wvp[r].y, a4.y);
                a4.z = fmaf(ev, wvp[r].z, a4.z); a4.w = fmaf(ev, wvp[r].w, a4.w);
            }
            a4.x += __shfl_xor_sync(0xffffffffu, a4.x, 16);
            a4.y += __shfl_xor_sync(0xffffffffu, a4.y, 16);
            a4.z += __shfl_xor_sync(0xffffffffu, a4.z, 16);
            a4.w += __shfl_xor_sync(0xffffffffu, a4.w, 16);
            if ((tc & 16) == 0)
                *(float4*)&S->red_f[0][w2][kq * 4] = a4;
        }
        __syncthreads();

        if (tid >= 256 && tid < 512 && i + 1 < L) {
            const float4* Wb = (const float4*)(W + (size_t)SE[i + 1] * (HDIM * HDIM));
            #pragma unroll
            for (int r = 0; r < 4; ++r) wvp[r] = Wb[(hp * 4 + r) * 16 + kq];
        }
        if (tid >= 64 && tid < 128 && i + 1 < L)
            S->bias_s[(i + 1) & 1][tid - 64] = Bb[(size_t)SE[i + 1] * HDIM + (tid - 64)];
        if (tid < 64) {
            float v = 0.0f;
            #pragma unroll
            for (int q = 0; q < 8; ++q) v += S->red_f[0][q][tid];
            v += S->bias_s[i & 1][tid] + S->pe[i][tid];
            float gev = gelu_exact(v);
            S->cache[i][tid] = gev;
            int base = (i + 1) * i / 2;
            float acc = 0.0f;
            for (int j = 0; j < i; ++j)
                acc = fmaf(S->wts[base + j], S->cache[j][tid], acc);
            e_vec[tid] = fmaf(S->wts[base + i], gev, acc);
        }
        __syncthreads();
    }

    // ---------------- generation priming (e_vec holds e for curr=L) ----------------
    if (tid == 0) S->x0 = (X0P != nullptr) ? X0P[0] : 7;
    __syncthreads();
    const int x0v = S->x0;

    int nn_reg = 0, nn_next = 0;
    if (tid < 32) {
        nn_reg = NN[(size_t)x0v * CNEI + tid];
        #pragma unroll
        for (int c = 0; c < 4; ++c)
            S->ne_br[tid][c] = NE[(size_t)nn_reg * CNEI + myrank * 4 + c];
    }
    if (tid < 4) S->edge0[tid] = NE[(size_t)x0v * CNEI + myrank * 4 + tid];
    __syncthreads();

    float4 wv[4];
    {
        const float4* Wb = (const float4*)(W + (size_t)S->edge0[g] * (HDIM * HDIM));
        #pragma unroll
        for (int r = 0; r < 4; ++r) wv[r] = Wb[(hp * 4 + r) * 16 + kq];
    }
    float bias_r = 0.0f;
    if (tid < 256) bias_r = Bb[(size_t)S->edge0[tid >> 6] * HDIM + (tid & 63)];

    cluster_sync_all();
    __syncthreads();

    // ---------------- generation loop (R13 champion + tail hoisting) ----------------
    for (int t = 0; t < T; ++t) {
        const int curr = L + t;
        const int cb   = t & 1;
        const uint32_t mb = cb ? mbar_a1 : mbar_a0;

        if (tid == 0) mbar_arrive_expect(mb, EXPECT_TX);

        // 1) matvec partials
        {
            float4 a4 = make_float4(0.f, 0.f, 0.f, 0.f);
            #pragma unroll
            for (int r = 0; r < 4; ++r) {
                float ev = e_vec[hp * 4 + r];
                a4.x = fmaf(ev, wv[r].x, a4.x); a4.y = fmaf(ev, wv[r].y, a4.y);
                a4.z = fmaf(ev, wv[r].z, a4.z); a4.w = fmaf(ev, wv[r].w, a4.w);
            }
            a4.x += __shfl_xor_sync(0xffffffffu, a4.x, 16);
            a4.y += __shfl_xor_sync(0xffffffffu, a4.y, 16);
            a4.z += __shfl_xor_sync(0xffffffffu, a4.z, 16);
            a4.w += __shfl_xor_sync(0xffffffffu, a4.w, 16);
            if ((tc & 16) == 0)
                *(float4*)&S->red_f[g][w2][kq * 4] = a4;
        }
        __syncthreads();   // bar1

        // 2) combine+gelu into push block | NE gathers | pooled partials
        if (tid < 256) {
            if (tid < 32 && t > 0) {
                nn_reg = nn_next;
                int e0 = NE[(size_t)nn_reg * CNEI + myrank * 4 + 0];
                int e1 = NE[(size_t)nn_reg * CNEI + myrank * 4 + 1];
                int e2 = NE[(size_t)nn_reg * CNEI + myrank * 4 + 2];
                int e3 = NE[(size_t)nn_reg * CNEI + myrank * 4 + 3];
                S->ne_br[lane][0] = e0; S->ne_br[lane][1] = e1;
                S->ne_br[lane][2] = e2; S->ne_br[lane][3] = e3;
            }
            int cand = tid >> 6, kk = tid & 63;
            float v = 0.0f;
            #pragma unroll
            for (int q = 0; q < 8; ++q) v += S->red_f[cand][q][kk];
            v += bias_r + S->pe[t][kk];
            float ge = gelu_exact(v);
            S->rx[cb][myrank].vec[cand][kk] = ge;
            float sq = ge * ge;
            #pragma unroll
            for (int off = 16; off > 0; off >>= 1)
                sq += __shfl_xor_sync(0xffffffffu, sq, off);
            if (lane == 0) S->rx[cb][myrank].en[tid >> 5] = sq;
        } else if (tid >= 512 && t + 1 < T) {
            int p = (tid >> 6) - 8, k = tid & 63;
            int base1 = (curr + 1) * curr / 2;
            float acc = 0.0f;
            for (int j = p; j < curr; j += 8)
                acc = fmaf(S->wts[base1 + j], S->cache[j][k], acc);
            S->red_s[p][k] = acc;
        }
        __syncthreads();   // bar2

        // 3) distributed push: lanes 0-6, staggered targets
        if (tid < NBLK - 1) {
            asm volatile("fence.proxy.async.shared::cta;" ::: "memory");
            uint32_t r = (myrank + 1 + (uint32_t)tid) & (NBLK - 1);
            uint32_t src = (uint32_t)__cvta_generic_to_shared(&S->rx[cb][myrank]);
            bulk_s2s(mapa_u32(src, r), src, PUSH_BYTES, mapa_u32(mb, r));
        }

        // 3b) pre-wait hoist: fold red_s + fetch wcur while the exchange flies
        float ee_pre = 0.0f, wcur = 0.0f;
        if (tid < HDIM && t + 1 < T) {
            int base1 = (curr + 1) * curr / 2;
            #pragma unroll
            for (int q = 0; q < 8; ++q) ee_pre += S->red_s[q][tid];
            wcur = S->wts[base1 + curr];
        }

        // 4) wait for all 7 peer blocks
        mbar_wait(mb, (uint32_t)((t >> 1) & 1));

        // 5) redundant per-warp argmax (uint order == float order, sumsq >= 0)
        int bi;
        {
            int rr = lane >> 2, cl = lane & 3;
            float2 eh = *(const float2*)&S->rx[cb][rr].en[cl * 2];
            float en = eh.x + eh.y;
            unsigned mx = __reduce_max_sync(0xffffffffu, __float_as_uint(en));
            unsigned msk = __ballot_sync(0xffffffffu, __float_as_uint(en) == mx);
            bi = __ffs(msk) - 1;      // first occurrence == jnp.argmax
        }
        if (tid < 32) {
            int y = __shfl_sync(0xffffffffu, nn_reg, bi);
            if (lane == 0) S->tok[t] = y;
            nn_next = NN[(size_t)y * CNEI + lane];
        }

        // 6) next-step weight/bias loads + winner read + short e-update
        {
            int edge_g = S->ne_br[bi][g];
            const float4* Wb = (const float4*)(W + (size_t)edge_g * (HDIM * HDIM));
            #pragma unroll
            for (int r = 0; r < 4; ++r) wv[r] = Wb[(hp * 4 + r) * 16 + kq];
        }
        if (tid < 256)
            bias_r = Bb[(size_t)S->ne_br[bi][tid >> 6] * HDIM + (tid & 63)];

        if (tid < HDIM) {
            float win = S->rx[cb][bi >> 2].vec[bi & 3][tid];
            S->cache[curr][tid] = win;
            if (t + 1 < T)
                e_vec[tid] = fmaf(wcur, win, ee_pre);
        }
        __syncthreads();   // bar4
    }

    // drain outgoing bulk reads before exit
    cluster_sync_all();
    __syncthreads();

    // ---------------- output (CTA 0) ----------------
    if (blockIdx.x == 0) {
        int ncache = (L + T) * HDIM;
        for (int i = tid; i < out_size; i += NTHR) {
            float v;
            if (i < ncache) v = S->cache[i >> 6][i & 63];
            else {
                int tt = i - ncache;
                v = (tt < T) ? (float)S->tok[tt] : 0.0f;
            }
            out[i] = v;
        }
    }
}

extern "C" void kernel_launch(void* const* d_in, const int* in_sizes, int n_in,
                              void* d_out, int out_size) {
    const float* W   = (const float*)d_in[0];
    const float* B   = (const float*)d_in[1];
    const float* POS = (const float*)d_in[2];
    const int*   SE  = (const int*)d_in[3];
    const int*   NE  = (const int*)d_in[4];
    const int*   NN  = (const int*)d_in[5];
    const int*   X0  = (n_in > 6) ? (const int*)d_in[6] : nullptr;
    const int*   MNT = (n_in > 7) ? (const int*)d_in[7] : nullptr;
    int L = in_sizes[3];

    cudaFuncSetAttribute(bralm_kernel,
                         cudaFuncAttributeMaxDynamicSharedMemorySize,
                         (int)sizeof(Smem));
    bralm_kernel<<<NBLK, NTHR, sizeof(Smem)>>>(W, B, POS, SE, NE, NN, X0, MNT,
                                               (float*)d_out, out_size, L);
}